// round 4
// baseline (speedup 1.0000x reference)
#include <cuda_runtime.h>
#include <cstdint>

#define NPTS 262144
#define DIMS 128
#define KCL  1024
#define TM   64     // points per block
#define TN   64     // clusters per tile
#define DC   64     // dim chunk

__device__ float g_csq[KCL];

// ---------------- cluster norms ----------------
__global__ void csq_kernel(const float* __restrict__ C) {
    int c = blockIdx.x * blockDim.x + threadIdx.x;
    if (c < KCL) {
        const float4* row = (const float4*)(C + (size_t)c * DIMS);
        float s = 0.f;
#pragma unroll
        for (int i = 0; i < DIMS / 4; i++) {
            float4 v = row[i];
            s += v.x * v.x + v.y * v.y + v.z * v.z + v.w * v.w;
        }
        g_csq[c] = s;
    }
}

// ---------------- fused distance + argmin ----------------
__global__ void __launch_bounds__(256)
kmeans_kernel(const float* __restrict__ X, const float* __restrict__ C,
              float* __restrict__ out)
{
    __shared__ float Xs[DIMS][TM];   // 32768 B, dim-major
    __shared__ float Cs[DC][TN];     // 16384 B, dim-major (one dim-chunk)

    const int t  = threadIdx.x;
    const int tx = t & 15;           // point group  (4 points)
    const int ty = t >> 4;           // cluster group (4 clusters)
    const int pbase = blockIdx.x * TM;

    // ---- load + transpose X tile (once per block) ----
    {
        const float4* Xg = (const float4*)(X + (size_t)pbase * DIMS);
#pragma unroll
        for (int k = 0; k < 8; k++) {
            int f  = t + 256 * k;    // 0..2047
            int p  = f & 63;         // point
            int c4 = f >> 6;         // float4 index in dims, 0..31
            float4 v = Xg[p * 32 + c4];
            Xs[4 * c4 + 0][p] = v.x;
            Xs[4 * c4 + 1][p] = v.y;
            Xs[4 * c4 + 2][p] = v.z;
            Xs[4 * c4 + 3][p] = v.w;
        }
    }
    __syncthreads();

    // ---- per-thread ||x||^2 for its 4 points ----
    float xsq[4] = {0.f, 0.f, 0.f, 0.f};
#pragma unroll 16
    for (int d = 0; d < DIMS; d++) {
        float4 xv = *(const float4*)&Xs[d][tx * 4];
        xsq[0] += xv.x * xv.x;
        xsq[1] += xv.y * xv.y;
        xsq[2] += xv.z * xv.z;
        xsq[3] += xv.w * xv.w;
    }

    float bd[4];
    int   bi[4];
#pragma unroll
    for (int j = 0; j < 4; j++) { bd[j] = 3.4e38f; bi[j] = 0; }

    for (int ct = 0; ct < KCL / TN; ct++) {
        float acc[4][4];
#pragma unroll
        for (int j = 0; j < 4; j++)
#pragma unroll
            for (int i = 0; i < 4; i++) acc[j][i] = 0.f;

#pragma unroll
        for (int dc = 0; dc < DIMS / DC; dc++) {
            __syncthreads();   // previous chunk's reads done
            // ---- load + transpose C chunk ----
            const float4* Cg = (const float4*)(C + (size_t)ct * TN * DIMS + dc * DC);
#pragma unroll
            for (int k = 0; k < 4; k++) {
                int f  = t + 256 * k;    // 0..1023
                int cl = f & 63;         // cluster within tile
                int c4 = f >> 6;         // float4 within chunk, 0..15
                float4 v = Cg[cl * 32 + c4];
                Cs[4 * c4 + 0][cl] = v.x;
                Cs[4 * c4 + 1][cl] = v.y;
                Cs[4 * c4 + 2][cl] = v.z;
                Cs[4 * c4 + 3][cl] = v.w;
            }
            __syncthreads();

#pragma unroll 16
            for (int d = 0; d < DC; d++) {
                float4 a = *(const float4*)&Xs[dc * DC + d][tx * 4];
                float4 b = *(const float4*)&Cs[d][ty * 4];
                acc[0][0] += a.x * b.x; acc[0][1] += a.x * b.y;
                acc[0][2] += a.x * b.z; acc[0][3] += a.x * b.w;
                acc[1][0] += a.y * b.x; acc[1][1] += a.y * b.y;
                acc[1][2] += a.y * b.z; acc[1][3] += a.y * b.w;
                acc[2][0] += a.z * b.x; acc[2][1] += a.z * b.y;
                acc[2][2] += a.z * b.z; acc[2][3] += a.z * b.w;
                acc[3][0] += a.w * b.x; acc[3][1] += a.w * b.y;
                acc[3][2] += a.w * b.z; acc[3][3] += a.w * b.w;
            }
        }

        // ---- tile epilogue: distance + running argmin (clusters ascending) ----
        int cb = ct * TN + ty * 4;
#pragma unroll
        for (int j = 0; j < 4; j++) {
#pragma unroll
            for (int i = 0; i < 4; i++) {
                float dis = (xsq[j] - 2.0f * acc[j][i]) + g_csq[cb + i];
                if (dis < bd[j]) { bd[j] = dis; bi[j] = cb + i; }
            }
        }
    }

    __syncthreads();
    // ---- cross-thread (over ty) argmin reduction, lexicographic (dis, idx) ----
    float* red_d = &Cs[0][0];          // 16*64 floats (fits in Cs)
    int*   red_i = (int*)&Xs[0][0];    // 16*64 ints   (fits in Xs)
#pragma unroll
    for (int j = 0; j < 4; j++) {
        red_d[ty * 64 + tx * 4 + j] = bd[j];
        red_i[ty * 64 + tx * 4 + j] = bi[j];
    }
    __syncthreads();
    if (t < TM) {
        float best  = red_d[t];
        int   besti = red_i[t];
#pragma unroll
        for (int y = 1; y < 16; y++) {
            float d   = red_d[y * 64 + t];
            int   idx = red_i[y * 64 + t];
            if (d < best || (d == best && idx < besti)) { best = d; besti = idx; }
        }
        // __output__ is float32: write the label as a FLOAT VALUE.
        out[pbase + t] = (float)besti;
    }
}

extern "C" void kernel_launch(void* const* d_in, const int* in_sizes, int n_in,
                              void* d_out, int out_size) {
    // Select inputs BY SIZE (robust to ordering):
    //   X: N*D = 33,554,432 floats;  cluster_centers: K*D = 131,072 floats.
    const float* X = (const float*)d_in[0];
    const float* C = (const float*)d_in[1];
    if (n_in >= 2 && in_sizes[0] < in_sizes[1]) {
        X = (const float*)d_in[1];
        C = (const float*)d_in[0];
    }
    float* out = (float*)d_out;

    csq_kernel<<<KCL / 256, 256>>>(C);
    kmeans_kernel<<<NPTS / TM, 256>>>(X, C, out);
}

// round 7
// speedup vs baseline: 2.3891x; 2.3891x over previous
#include <cuda_runtime.h>
#include <cuda_bf16.h>
#include <cstdint>

#define NPTS 262144
#define DIMS 128
#define KCL  1024
#define TM   128
#define TN   128
#define NTILES (KCL / TN)   // 8

// ---- smem map (dynamic, from 1KB-aligned base) ----
#define SM_XHI 0
#define SM_XLO 32768
#define SM_C   65536            // 2 buffers x (hi 32K + lo 32K)
#define SM_CSQ (65536 + 131072) // 4KB
#define SM_BYTES (SM_CSQ + 4096 + 1024)

__device__ float g_csq[KCL];
__device__ __align__(16) unsigned char g_chi[KCL * DIMS * 2];  // bf16, row-major [k][d]
__device__ __align__(16) unsigned char g_clo[KCL * DIMS * 2];

// ---------------- PTX helpers (sm_80+ baseline ISA only) ----------------
__device__ __forceinline__ uint32_t smem_u32(const void* p) {
    uint32_t a;
    asm("{ .reg .u64 t; cvta.to.shared.u64 t, %1; cvt.u32.u64 %0, t; }" : "=r"(a) : "l"(p));
    return a;
}
#define LDSM_X4(r0, r1, r2, r3, addr) \
    asm volatile("ldmatrix.sync.aligned.m8n8.x4.shared.b16 {%0,%1,%2,%3}, [%4];" \
                 : "=r"(r0), "=r"(r1), "=r"(r2), "=r"(r3) : "r"(addr))
#define MMA_BF16(d, a, b) \
    asm volatile("mma.sync.aligned.m16n8k16.row.col.f32.bf16.bf16.f32 " \
                 "{%0,%1,%2,%3}, {%4,%5,%6,%7}, {%8,%9}, {%0,%1,%2,%3};" \
                 : "+f"((d)[0]), "+f"((d)[1]), "+f"((d)[2]), "+f"((d)[3]) \
                 : "r"((a)[0]), "r"((a)[1]), "r"((a)[2]), "r"((a)[3]), \
                   "r"((b)[0]), "r"((b)[1]))
#define CP_ASYNC16(dst, src) \
    asm volatile("cp.async.cg.shared.global [%0], [%1], 16;" :: "r"(dst), "l"(src))
#define CP_COMMIT() asm volatile("cp.async.commit_group;" ::: "memory")
#define CP_WAIT(n)  asm volatile("cp.async.wait_group %0;" :: "n"(n) : "memory")

// ---------------- prep kernels ----------------
__global__ void csq_kernel(const float* __restrict__ C) {
    int c = blockIdx.x * blockDim.x + threadIdx.x;
    if (c < KCL) {
        const float4* row = (const float4*)(C + (size_t)c * DIMS);
        float s = 0.f;
#pragma unroll
        for (int i = 0; i < DIMS / 4; i++) {
            float4 v = row[i];
            s += v.x * v.x + v.y * v.y + v.z * v.z + v.w * v.w;
        }
        g_csq[c] = s;
    }
}

__global__ void csplit_kernel(const float* __restrict__ C) {
    int idx = blockIdx.x * blockDim.x + threadIdx.x;   // over K*D
    if (idx < KCL * DIMS) {
        float v = C[idx];
        __nv_bfloat16 hi = __float2bfloat16(v);
        __nv_bfloat16 lo = __float2bfloat16(v - __bfloat162float(hi));
        *(__nv_bfloat16*)(g_chi + (size_t)idx * 2) = hi;
        *(__nv_bfloat16*)(g_clo + (size_t)idx * 2) = lo;
    }
}

// ---------------- main fused kernel ----------------
__global__ void __launch_bounds__(256, 1)
kmeans_mma_kernel(const float* __restrict__ X, const float* __restrict__ Cf,
                  float* __restrict__ out)
{
    extern __shared__ unsigned char smraw[];
    uint32_t base = (smem_u32(smraw) + 1023u) & ~1023u;
    unsigned char* sm = smraw + (base - smem_u32(smraw));

    const int t    = threadIdx.x;
    const int lane = t & 31;
    const int wid  = t >> 5;
    const int wm   = wid & 3;    // warp row  (32 pts)
    const int wn   = wid >> 2;   // warp col  (64 clusters)
    const int pbase = blockIdx.x * TM;

    auto cp_tile = [&](int ct, int buf) {
        uint32_t dbase = base + SM_C + buf * 65536;
#pragma unroll
        for (int i = 0; i < 8; i++) {
            int idx = t + 256 * i;
            int row = idx >> 4;
            int c   = idx & 15;
            uint32_t doff = (uint32_t)row * 256 + (uint32_t)((c ^ (row & 7)) << 4);
            size_t   soff = (size_t)ct * 32768 + (size_t)row * 256 + (size_t)c * 16;
            CP_ASYNC16(dbase + doff,         g_chi + soff);
            CP_ASYNC16(dbase + 32768 + doff, g_clo + soff);
        }
        CP_COMMIT();
    };
    cp_tile(0, 0);
    cp_tile(1, 1);

    float* csq_s = (float*)(sm + SM_CSQ);
#pragma unroll
    for (int k = 0; k < 4; k++) csq_s[t + 256 * k] = g_csq[t + 256 * k];

    // ---- build X hi/lo tiles in smem (swizzled 256B rows) ----
    {
        const float4* Xg = (const float4*)(X + (size_t)pbase * DIMS);
#pragma unroll
        for (int i = 0; i < 8; i++) {
            int idx = t + 256 * i;
            int row = idx >> 4;
            int c   = idx & 15;
            float4 v0 = Xg[row * 32 + c * 2];
            float4 v1 = Xg[row * 32 + c * 2 + 1];
            float f[8] = {v0.x, v0.y, v0.z, v0.w, v1.x, v1.y, v1.z, v1.w};
            union { __nv_bfloat16 b[8]; uint4 u; } ph, pl;
#pragma unroll
            for (int e = 0; e < 8; e++) {
                __nv_bfloat16 h = __float2bfloat16(f[e]);
                ph.b[e] = h;
                pl.b[e] = __float2bfloat16(f[e] - __bfloat162float(h));
            }
            uint32_t doff = (uint32_t)row * 256 + (uint32_t)((c ^ (row & 7)) << 4);
            *(uint4*)(sm + SM_XHI + doff) = ph.u;
            *(uint4*)(sm + SM_XLO + doff) = pl.u;
        }
    }

    const int arow0 = wm * 32 + (lane & 15);
    const uint32_t akb = (uint32_t)(lane >> 4) * 16;
    const int brow0 = wn * 64 + (lane & 7) + ((lane >> 4) << 3);
    const uint32_t bkb = (uint32_t)((lane >> 3) & 1) * 16;

    // top-2 trackers per owned (point, col-pair) slot: j = mi*2 + h
    float b1[4], b2[4];
    int   i1[4], i2[4];
#pragma unroll
    for (int j = 0; j < 4; j++) { b1[j] = 3.4e38f; b2[j] = 3.4e38f; i1[j] = 0; i2[j] = 1; }
    const int r  = lane >> 2;
    const int c2 = (lane & 3) * 2;

    for (int ct = 0; ct < NTILES; ct++) {
        if (ct < NTILES - 1) { CP_WAIT(1); } else { CP_WAIT(0); }
        __syncthreads();

        const uint32_t chb = base + SM_C + (ct & 1) * 65536;
        const uint32_t clb = chb + 32768;

        float acc[2][8][4];
#pragma unroll
        for (int mi = 0; mi < 2; mi++)
#pragma unroll
            for (int ni = 0; ni < 8; ni++)
#pragma unroll
                for (int q = 0; q < 4; q++) acc[mi][ni][q] = 0.f;

#pragma unroll
        for (int ks = 0; ks < 8; ks++) {
            uint32_t ahi[2][4], alo[2][4], bhi[8][2], blo[8][2];
#pragma unroll
            for (int mi = 0; mi < 2; mi++) {
                int row = arow0 + mi * 16;
                uint32_t off = (uint32_t)row * 256 +
                               (((uint32_t)ks * 32 + akb) ^ (uint32_t)((row & 7) << 4));
                LDSM_X4(ahi[mi][0], ahi[mi][1], ahi[mi][2], ahi[mi][3], base + SM_XHI + off);
                LDSM_X4(alo[mi][0], alo[mi][1], alo[mi][2], alo[mi][3], base + SM_XLO + off);
            }
#pragma unroll
            for (int nh = 0; nh < 4; nh++) {
                int row = brow0 + nh * 16;
                uint32_t off = (uint32_t)row * 256 +
                               (((uint32_t)ks * 32 + bkb) ^ (uint32_t)((row & 7) << 4));
                LDSM_X4(bhi[2 * nh][0], bhi[2 * nh][1], bhi[2 * nh + 1][0], bhi[2 * nh + 1][1],
                        chb + off);
                LDSM_X4(blo[2 * nh][0], blo[2 * nh][1], blo[2 * nh + 1][0], blo[2 * nh + 1][1],
                        clb + off);
            }
#pragma unroll
            for (int mi = 0; mi < 2; mi++)
#pragma unroll
                for (int ni = 0; ni < 8; ni++) {
                    MMA_BF16(acc[mi][ni], ahi[mi], bhi[ni]);
                    MMA_BF16(acc[mi][ni], ahi[mi], blo[ni]);
                    MMA_BF16(acc[mi][ni], alo[mi], bhi[ni]);
                }
        }

        // ---- tile epilogue: score = csq - 2*cross, running TOP-2 ----
#pragma unroll
        for (int mi = 0; mi < 2; mi++)
#pragma unroll
            for (int ni = 0; ni < 8; ni++) {
                int cb = ct * TN + wn * 64 + ni * 8 + c2;
#pragma unroll
                for (int q = 0; q < 4; q++) {
                    int j = mi * 2 + (q >> 1);
                    int c = cb + (q & 1);
                    float s = fmaf(acc[mi][ni][q], -2.f, csq_s[c]);
                    if (s < b1[j]) { b2[j] = b1[j]; i2[j] = i1[j]; b1[j] = s; i1[j] = c; }
                    else if (s < b2[j]) { b2[j] = s; i2[j] = c; }
                }
            }

        __syncthreads();
        if (ct + 2 < NTILES) cp_tile(ct + 2, ct & 1);
    }

    // ---- cross-lane/warp top-2 reduction (reuse C buffer smem) ----
    float4* rd4 = (float4*)(sm + SM_C);   // [128][8] slots of {b1, b2, i1, i2}
    int slot = wn * 4 + (lane & 3);
#pragma unroll
    for (int mi = 0; mi < 2; mi++)
#pragma unroll
        for (int h = 0; h < 2; h++) {
            int j = mi * 2 + h;
            int row = wm * 32 + mi * 16 + h * 8 + r;
            float4 v;
            v.x = b1[j]; v.y = b2[j];
            v.z = __int_as_float(i1[j]); v.w = __int_as_float(i2[j]);
            rd4[row * 8 + slot] = v;
        }
    __syncthreads();

    if (t < TM) {
        float g1 = 3.4e38f, g2 = 3.4e38f;
        int   j1 = 0,        j2 = 1;
#pragma unroll
        for (int s = 0; s < 8; s++) {
            float4 v = rd4[t * 8 + s];
            float sb[2] = {v.x, v.y};
            int   si[2] = {__float_as_int(v.z), __float_as_int(v.w)};
#pragma unroll
            for (int e = 0; e < 2; e++) {
                float sc = sb[e]; int ci = si[e];
                if (sc < g1 || (sc == g1 && ci < j1)) {
                    g2 = g1; j2 = j1; g1 = sc; j1 = ci;
                } else if (sc < g2 || (sc == g2 && ci < j2)) {
                    g2 = sc; j2 = ci;
                }
            }
        }

        // ---- exact fp32 re-check of the two candidates ----
        const float4* xr = (const float4*)(X + (size_t)(pbase + t) * DIMS);
        const float4* p1 = (const float4*)(Cf + (size_t)j1 * DIMS);
        const float4* p2 = (const float4*)(Cf + (size_t)j2 * DIMS);
        float a1 = 0.f, a2 = 0.f, a3 = 0.f, a4 = 0.f;
        float e1 = 0.f, e2 = 0.f, e3 = 0.f, e4 = 0.f;
#pragma unroll 8
        for (int i = 0; i < DIMS / 4; i++) {
            float4 xv = xr[i], u = p1[i], w = p2[i];
            a1 += xv.x * u.x; a2 += xv.y * u.y; a3 += xv.z * u.z; a4 += xv.w * u.w;
            e1 += xv.x * w.x; e2 += xv.y * w.y; e3 += xv.z * w.z; e4 += xv.w * w.w;
        }
        float cr1 = (a1 + a2) + (a3 + a4);
        float cr2 = (e1 + e2) + (e3 + e4);
        float s1 = fmaf(cr1, -2.f, csq_s[j1]);
        float s2 = fmaf(cr2, -2.f, csq_s[j2]);
        int lab = (s2 < s1 || (s2 == s1 && j2 < j1)) ? j2 : j1;
        out[pbase + t] = (float)lab;   // __output__ is float32
    }
}

extern "C" void kernel_launch(void* const* d_in, const int* in_sizes, int n_in,
                              void* d_out, int out_size) {
    const float* X = (const float*)d_in[0];
    const float* C = (const float*)d_in[1];
    if (n_in >= 2 && in_sizes[0] < in_sizes[1]) {
        X = (const float*)d_in[1];
        C = (const float*)d_in[0];
    }
    float* out = (float*)d_out;

    cudaFuncSetAttribute(kmeans_mma_kernel,
                         cudaFuncAttributeMaxDynamicSharedMemorySize, SM_BYTES);

    csq_kernel<<<KCL / 256, 256>>>(C);
    csplit_kernel<<<KCL * DIMS / 256, 256>>>(C);
    kmeans_mma_kernel<<<NPTS / TM, 256, SM_BYTES>>>(X, C, out);
}

// round 8
// speedup vs baseline: 2.6114x; 1.0930x over previous
#include <cuda_runtime.h>
#include <cuda_bf16.h>
#include <cstdint>

#define NPTS 262144
#define DIMS 128
#define KCL  1024
#define TM   128
#define TN   128
#define NTILES (KCL / TN)   // 8

// ---- smem map (dynamic, from 1KB-aligned base) ----
#define SM_XHI 0
#define SM_XLO 32768
#define SM_C   65536            // 2 buffers x (hi 32K + lo 32K)
#define SM_CSQ (65536 + 131072) // 4KB
#define SM_BYTES (SM_CSQ + 4096 + 1024)

__device__ float g_csq[KCL];
__device__ __align__(16) unsigned char g_chi[KCL * DIMS * 2];  // bf16, row-major [k][d]
__device__ __align__(16) unsigned char g_clo[KCL * DIMS * 2];

// ---------------- PTX helpers (sm_80+ baseline ISA only) ----------------
__device__ __forceinline__ uint32_t smem_u32(const void* p) {
    uint32_t a;
    asm("{ .reg .u64 t; cvta.to.shared.u64 t, %1; cvt.u32.u64 %0, t; }" : "=r"(a) : "l"(p));
    return a;
}
#define LDSM_X4(r0, r1, r2, r3, addr) \
    asm volatile("ldmatrix.sync.aligned.m8n8.x4.shared.b16 {%0,%1,%2,%3}, [%4];" \
                 : "=r"(r0), "=r"(r1), "=r"(r2), "=r"(r3) : "r"(addr))
#define MMA_BF16(d, a, b) \
    asm volatile("mma.sync.aligned.m16n8k16.row.col.f32.bf16.bf16.f32 " \
                 "{%0,%1,%2,%3}, {%4,%5,%6,%7}, {%8,%9}, {%0,%1,%2,%3};" \
                 : "+f"((d)[0]), "+f"((d)[1]), "+f"((d)[2]), "+f"((d)[3]) \
                 : "r"((a)[0]), "r"((a)[1]), "r"((a)[2]), "r"((a)[3]), \
                   "r"((b)[0]), "r"((b)[1]))
#define CP_ASYNC16(dst, src) \
    asm volatile("cp.async.cg.shared.global [%0], [%1], 16;" :: "r"(dst), "l"(src))
#define CP_COMMIT() asm volatile("cp.async.commit_group;" ::: "memory")
#define CP_WAIT(n)  asm volatile("cp.async.wait_group %0;" :: "n"(n) : "memory")

// ---------------- merged prep kernel (csq + bf16 split) ----------------
__global__ void prep_kernel(const float* __restrict__ C) {
    int idx = blockIdx.x * blockDim.x + threadIdx.x;   // over K*D
    if (idx < KCL * DIMS) {
        float v = C[idx];
        __nv_bfloat16 hi = __float2bfloat16(v);
        __nv_bfloat16 lo = __float2bfloat16(v - __bfloat162float(hi));
        *(__nv_bfloat16*)(g_chi + (size_t)idx * 2) = hi;
        *(__nv_bfloat16*)(g_clo + (size_t)idx * 2) = lo;
    }
    if (idx < KCL) {
        const float4* row = (const float4*)(C + (size_t)idx * DIMS);
        float s = 0.f;
#pragma unroll
        for (int i = 0; i < DIMS / 4; i++) {
            float4 v = row[i];
            s += v.x * v.x + v.y * v.y + v.z * v.z + v.w * v.w;
        }
        g_csq[idx] = s;
    }
}

// ---------------- main fused kernel ----------------
__global__ void __launch_bounds__(256, 1)
kmeans_mma_kernel(const float* __restrict__ X, const float* __restrict__ Cf,
                  float* __restrict__ out)
{
    extern __shared__ unsigned char smraw[];
    uint32_t base = (smem_u32(smraw) + 1023u) & ~1023u;
    unsigned char* sm = smraw + (base - smem_u32(smraw));

    const int t    = threadIdx.x;
    const int lane = t & 31;
    const int wid  = t >> 5;
    const int wm   = wid & 3;    // warp row  (32 pts)
    const int wn   = wid >> 2;   // warp col  (64 clusters)
    const int pbase = blockIdx.x * TM;

    auto cp_tile = [&](int ct, int buf) {
        uint32_t dbase = base + SM_C + buf * 65536;
#pragma unroll
        for (int i = 0; i < 8; i++) {
            int idx = t + 256 * i;
            int row = idx >> 4;
            int c   = idx & 15;
            uint32_t doff = (uint32_t)row * 256 + (uint32_t)((c ^ (row & 7)) << 4);
            size_t   soff = (size_t)ct * 32768 + (size_t)row * 256 + (size_t)c * 16;
            CP_ASYNC16(dbase + doff,         g_chi + soff);
            CP_ASYNC16(dbase + 32768 + doff, g_clo + soff);
        }
        CP_COMMIT();
    };
    cp_tile(0, 0);
    cp_tile(1, 1);

    float* csq_s = (float*)(sm + SM_CSQ);
#pragma unroll
    for (int k = 0; k < 4; k++) csq_s[t + 256 * k] = g_csq[t + 256 * k];

    // ---- build X hi/lo tiles in smem (swizzled 256B rows) ----
    {
        const float4* Xg = (const float4*)(X + (size_t)pbase * DIMS);
#pragma unroll
        for (int i = 0; i < 8; i++) {
            int idx = t + 256 * i;
            int row = idx >> 4;
            int c   = idx & 15;
            float4 v0 = Xg[row * 32 + c * 2];
            float4 v1 = Xg[row * 32 + c * 2 + 1];
            float f[8] = {v0.x, v0.y, v0.z, v0.w, v1.x, v1.y, v1.z, v1.w};
            union { __nv_bfloat16 b[8]; uint4 u; } ph, pl;
#pragma unroll
            for (int e = 0; e < 8; e++) {
                __nv_bfloat16 h = __float2bfloat16(f[e]);
                ph.b[e] = h;
                pl.b[e] = __float2bfloat16(f[e] - __bfloat162float(h));
            }
            uint32_t doff = (uint32_t)row * 256 + (uint32_t)((c ^ (row & 7)) << 4);
            *(uint4*)(sm + SM_XHI + doff) = ph.u;
            *(uint4*)(sm + SM_XLO + doff) = pl.u;
        }
    }

    const int arow0 = wm * 32 + (lane & 15);
    const uint32_t akb = (uint32_t)(lane >> 4) * 16;
    const int brow0 = wn * 64 + (lane & 7) + ((lane >> 4) << 3);
    const uint32_t bkb = (uint32_t)((lane >> 3) & 1) * 16;

    // branchless top-2: packed keys (sortable_score << 32) | cluster_idx
    uint64_t k1[4], k2[4];
#pragma unroll
    for (int j = 0; j < 4; j++) { k1[j] = ~0ull; k2[j] = ~0ull; }
    const int r  = lane >> 2;
    const int c2 = (lane & 3) * 2;

    for (int ct = 0; ct < NTILES; ct++) {
        if (ct < NTILES - 1) { CP_WAIT(1); } else { CP_WAIT(0); }
        __syncthreads();

        const uint32_t chb = base + SM_C + (ct & 1) * 65536;
        const uint32_t clb = chb + 32768;

        float acc[2][8][4];
#pragma unroll
        for (int mi = 0; mi < 2; mi++)
#pragma unroll
            for (int ni = 0; ni < 8; ni++)
#pragma unroll
                for (int q = 0; q < 4; q++) acc[mi][ni][q] = 0.f;

#pragma unroll
        for (int ks = 0; ks < 8; ks++) {
            uint32_t ahi[2][4], alo[2][4], bhi[8][2], blo[8][2];
#pragma unroll
            for (int mi = 0; mi < 2; mi++) {
                int row = arow0 + mi * 16;
                uint32_t off = (uint32_t)row * 256 +
                               (((uint32_t)ks * 32 + akb) ^ (uint32_t)((row & 7) << 4));
                LDSM_X4(ahi[mi][0], ahi[mi][1], ahi[mi][2], ahi[mi][3], base + SM_XHI + off);
                LDSM_X4(alo[mi][0], alo[mi][1], alo[mi][2], alo[mi][3], base + SM_XLO + off);
            }
#pragma unroll
            for (int nh = 0; nh < 4; nh++) {
                int row = brow0 + nh * 16;
                uint32_t off = (uint32_t)row * 256 +
                               (((uint32_t)ks * 32 + bkb) ^ (uint32_t)((row & 7) << 4));
                LDSM_X4(bhi[2 * nh][0], bhi[2 * nh][1], bhi[2 * nh + 1][0], bhi[2 * nh + 1][1],
                        chb + off);
                LDSM_X4(blo[2 * nh][0], blo[2 * nh][1], blo[2 * nh + 1][0], blo[2 * nh + 1][1],
                        clb + off);
            }
#pragma unroll
            for (int mi = 0; mi < 2; mi++)
#pragma unroll
                for (int ni = 0; ni < 8; ni++) {
                    MMA_BF16(acc[mi][ni], ahi[mi], bhi[ni]);
                    MMA_BF16(acc[mi][ni], ahi[mi], blo[ni]);
                    MMA_BF16(acc[mi][ni], alo[mi], bhi[ni]);
                }
        }

        // ---- tile epilogue: score = csq - 2*cross, BRANCHLESS top-2 ----
#pragma unroll
        for (int mi = 0; mi < 2; mi++)
#pragma unroll
            for (int ni = 0; ni < 8; ni++) {
                int cb = ct * TN + wn * 64 + ni * 8 + c2;
#pragma unroll
                for (int q = 0; q < 4; q++) {
                    int j = mi * 2 + (q >> 1);
                    uint32_t cidx = (uint32_t)(cb + (q & 1));
                    float s = fmaf(acc[mi][ni][q], -2.f, csq_s[cidx]);
                    uint32_t b = __float_as_uint(s);
                    uint32_t u = b ^ (uint32_t)(((int32_t)b >> 31) | 0x80000000);
                    uint64_t k = ((uint64_t)u << 32) | cidx;
                    bool p = k < k1[j];
                    uint64_t m = p ? k1[j] : k;
                    k1[j] = p ? k : k1[j];
                    k2[j] = (m < k2[j]) ? m : k2[j];
                }
            }

        __syncthreads();
        if (ct + 2 < NTILES) cp_tile(ct + 2, ct & 1);
    }

    // ---- cross-lane/warp top-2 reduction (reuse C buffer smem) ----
    uint64_t* rd = (uint64_t*)(sm + SM_C);   // [128][8 slots][2]
    int slot = wn * 4 + (lane & 3);
#pragma unroll
    for (int mi = 0; mi < 2; mi++)
#pragma unroll
        for (int h = 0; h < 2; h++) {
            int j = mi * 2 + h;
            int row = wm * 32 + mi * 16 + h * 8 + r;
            rd[row * 16 + slot * 2 + 0] = k1[j];
            rd[row * 16 + slot * 2 + 1] = k2[j];
        }
    __syncthreads();

    if (t < TM) {
        uint64_t g1 = ~0ull, g2 = ~0ull;
#pragma unroll
        for (int s = 0; s < 16; s++) {
            uint64_t k = rd[t * 16 + s];
            bool p = k < g1;
            uint64_t m = p ? g1 : k;
            g1 = p ? k : g1;
            g2 = (m < g2) ? m : g2;
        }
        int j1 = (int)(uint32_t)g1;
        int j2 = (int)(uint32_t)g2;

        // ---- exact fp32 re-check of the two candidates ----
        const float4* xr = (const float4*)(X + (size_t)(pbase + t) * DIMS);
        const float4* p1 = (const float4*)(Cf + (size_t)j1 * DIMS);
        const float4* p2 = (const float4*)(Cf + (size_t)j2 * DIMS);
        float a1 = 0.f, a2 = 0.f, a3 = 0.f, a4 = 0.f;
        float e1 = 0.f, e2 = 0.f, e3 = 0.f, e4 = 0.f;
#pragma unroll 8
        for (int i = 0; i < DIMS / 4; i++) {
            float4 xv = xr[i], u = p1[i], w = p2[i];
            a1 += xv.x * u.x; a2 += xv.y * u.y; a3 += xv.z * u.z; a4 += xv.w * u.w;
            e1 += xv.x * w.x; e2 += xv.y * w.y; e3 += xv.z * w.z; e4 += xv.w * w.w;
        }
        float cr1 = (a1 + a2) + (a3 + a4);
        float cr2 = (e1 + e2) + (e3 + e4);
        float s1 = fmaf(cr1, -2.f, csq_s[j1]);
        float s2 = fmaf(cr2, -2.f, csq_s[j2]);
        int lab = (s2 < s1 || (s2 == s1 && j2 < j1)) ? j2 : j1;
        out[pbase + t] = (float)lab;   // __output__ is float32
    }
}

extern "C" void kernel_launch(void* const* d_in, const int* in_sizes, int n_in,
                              void* d_out, int out_size) {
    const float* X = (const float*)d_in[0];
    const float* C = (const float*)d_in[1];
    if (n_in >= 2 && in_sizes[0] < in_sizes[1]) {
        X = (const float*)d_in[1];
        C = (const float*)d_in[0];
    }
    float* out = (float*)d_out;

    cudaFuncSetAttribute(kmeans_mma_kernel,
                         cudaFuncAttributeMaxDynamicSharedMemorySize, SM_BYTES);

    prep_kernel<<<KCL * DIMS / 256, 256>>>(C);
    kmeans_mma_kernel<<<NPTS / TM, 256, SM_BYTES>>>(X, C, out);
}